// round 7
// baseline (speedup 1.0000x reference)
#include <cuda_runtime.h>
#include <math.h>

#define NB 16
#define NT 50
#define NA 3
#define NG 76
#define PLANE (NG*NG)            // 5776
#define NC 85
#define CH (NA*NC)               // 255
#define NBT (NB*NT)              // 800
#define CELL_WORDS 181           // ceil(5776/32)
#define TOTAL_CONF (NB*NA*PLANE) // 277248
#define THREADS 1024
#define DENSE_BLOCKS 132
#define GRID 148                 // 132 dense + 16 builders, one wave
#define PLANE4 (PLANE/4)         // 1444
#define TOTAL4 (48*PLANE4)       // 69312
#define BASE_CHUNK (TOTAL4/DENSE_BLOCKS)          // 525
#define EXTRA (TOTAL4 - BASE_CHUNK*DENSE_BLOCKS)  // 12

// ---------------- device scratch (tickets/bitmap self-reset each replay) ----
__device__ float    g_dense[DENSE_BLOCKS];
__device__ float    g_bb[NB*6];          // per-batch: sx, sy, sw, sh, sobj, nm
__device__ int      g_wcell[NBT];        // winner cell or -1
__device__ float    g_wsp4[NBT];         // winner softplus(p4)
__device__ unsigned g_zero[CELL_WORDS];  // ignore-cell union (zero-init)
__device__ float    g_tail[4];           // corr_sum, mcs, mcc, nzf
__device__ int      g_bdone;             // builder ticket
__device__ int      g_done;              // global ticket

__device__ __forceinline__ float softplus_f(float v) {
    float a = fabsf(v);
    return fmaxf(v, 0.f) + __logf(1.f + __expf(-a));
}

__device__ __forceinline__ float block_reduce1024(float v, float* sh) {
    int lane = threadIdx.x & 31, wid = threadIdx.x >> 5;
    #pragma unroll
    for (int o = 16; o; o >>= 1) v += __shfl_down_sync(0xffffffffu, v, o);
    if (lane == 0) sh[wid] = v;
    __syncthreads();
    if (wid == 0) {
        v = sh[lane];   // exactly 32 warps
        #pragma unroll
        for (int o = 16; o; o >>= 1) v += __shfl_down_sync(0xffffffffu, v, o);
    }
    __syncthreads();
    return v;           // valid in thread 0
}

__global__ __launch_bounds__(THREADS, 1)
void k_yolo(const float* __restrict__ sample,
            const float* __restrict__ targets,
            const float* __restrict__ anchors,
            float* __restrict__ out)
{
    __shared__ int      s_key[NT];
    __shared__ float    s_gx[NT], s_gy[NT], s_gw[NT], s_gh[NT];
    __shared__ float    s_slot[NT][6];
    __shared__ unsigned c_zero[CELL_WORDS];
    __shared__ int      s_zlist[256];
    __shared__ int      s_nz;
    __shared__ float    s_red[32];
    __shared__ float    s_f[6];
    __shared__ float    s_t[4];
    __shared__ int      s_flag;

    const int tid = threadIdx.x;
    const int blk = blockIdx.x;

    if (blk < DENSE_BLOCKS) {
        // ------------- dense softplus, ~525 float4 per block, 1 round -------------
        int start = blk * BASE_CHUNK + min(blk, EXTRA);
        int cnt   = BASE_CHUNK + (blk < EXTRA ? 1 : 0);
        float s = 0.f;
        if (tid < cnt) {
            int gi4 = start + tid;
            int plane = gi4 / PLANE4;       // (b,a) conf plane: channel 85*plane+4
            int off   = gi4 - plane * PLANE4;
            const float4* c4 = (const float4*)sample + (size_t)(85 * plane + 4) * PLANE4 + off;
            float4 v = *c4;
            float srelu = fmaxf(v.x, 0.f) + fmaxf(v.y, 0.f)
                        + fmaxf(v.z, 0.f) + fmaxf(v.w, 0.f);
            float p = (1.f + __expf(-fabsf(v.x)))
                    * (1.f + __expf(-fabsf(v.y)))
                    * (1.f + __expf(-fabsf(v.z)))
                    * (1.f + __expf(-fabsf(v.w)));
            s = srelu + __logf(p);          // 4 exp + 1 log per float4
        }
        float rs = block_reduce1024(s, s_red);
        if (tid == 0) { g_dense[blk] = rs; __threadfence(); }
    } else {
        // ------------- builder block for batch b: 50 targets -------------
        const int b = blk - DENSE_BLOCKS;
        const float stride = 608.0f / (float)NG;   // 8
        float awS[NA], ahS[NA];
        #pragma unroll
        for (int a = 0; a < NA; a++) {
            awS[a] = anchors[2*a]   / stride;
            ahS[a] = anchors[2*a+1] / stride;
        }
        if (tid == 0) s_nz = 0;

        if (tid < NT) {
            const float* tg = targets + (size_t)(b*NT + tid) * 5;
            const float* t0 = targets + (size_t)(b*NT) * 5;
            float s5 = tg[0] + tg[1] + tg[2] + tg[3] + tg[4];
            bool mm = s5 > 0.f;
            float gx = (mm ? tg[1] : t0[1]) * NG;
            float gy = (mm ? tg[2] : t0[2]) * NG;
            float gw = (mm ? tg[3] : t0[3]) * NG;
            float gh = (mm ? tg[4] : t0[4]) * NG;
            int gi = (int)gx, gj = (int)gy;

            float best = -1e30f; int bn = 0; bool ign = false;
            #pragma unroll
            for (int a = 0; a < NA; a++) {
                float iw = fminf(gw, awS[a]) + 1.f;
                float ih = fminf(gh, ahS[a]) + 1.f;
                float inter = fmaxf(iw, 0.f) * fmaxf(ih, 0.f);
                float denom = (gw + 1.f) * (gh + 1.f)
                            + (awS[a] + 1.f) * (ahS[a] + 1.f) - inter + 1e-12f;
                float iou = __fdividef(inter, denom);
                ign |= (iou > 0.5f);
                if (iou > best) { best = iou; bn = a; }  // first-max wins ties
            }
            int cell = gj * NG + gi;
            if (ign) atomicOr(&g_zero[cell >> 5], 1u << (cell & 31));
            s_key[tid] = bn * PLANE + cell;              // within-batch key
            s_gx[tid] = gx; s_gy[tid] = gy; s_gw[tid] = gw; s_gh[tid] = gh;
        }
        __syncthreads();

        if (tid < NT) {
            int mykey = s_key[tid];
            bool winner = true;                          // last-wins scan
            #pragma unroll
            for (int t2 = 0; t2 < NT; t2++)
                winner &= !((t2 > tid) & (s_key[t2] == mykey));

            float a0=0.f,a1=0.f,a2=0.f,a3=0.f,a4=0.f,a5=0.f;
            int wc = -1; float wsp = 0.f;
            if (winner) {
                float gx = s_gx[tid], gy = s_gy[tid], gw = s_gw[tid], gh = s_gh[tid];
                int cell = mykey % PLANE;
                int bn   = mykey / PLANE;
                int gi = (int)gx, gj = (int)gy;
                size_t off = ((size_t)(b * CH + bn * NC)) * PLANE + (size_t)cell;
                float p0 = sample[off];
                float p1 = sample[off + 1 * PLANE];
                float p2 = sample[off + 2 * PLANE];
                float p3 = sample[off + 3 * PLANE];
                float p4 = sample[off + 4 * PLANE];

                float x  = __fdividef(1.f, 1.f + __expf(-p0));
                float y  = __fdividef(1.f, 1.f + __expf(-p1));
                float pc = __fdividef(1.f, 1.f + __expf(-p4));
                float tx = gx - (float)gi;
                float ty = gy - (float)gj;
                float tw = __logf(__fdividef(gw, awS[bn]) + 1e-16f);
                float th = __logf(__fdividef(gh, ahS[bn]) + 1e-16f);

                float dx = x - tx, dy = y - ty, dw = p2 - tw, dh = p3 - th;
                a0 = dx*dx; a1 = dy*dy; a2 = dw*dw; a3 = dh*dh;
                a4 = -__logf(pc + 1e-12f);
                a5 = 1.f;
                wc = cell; wsp = softplus_f(p4);
            }
            s_slot[tid][0]=a0; s_slot[tid][1]=a1; s_slot[tid][2]=a2;
            s_slot[tid][3]=a3; s_slot[tid][4]=a4; s_slot[tid][5]=a5;
            g_wcell[b*NT + tid] = wc;
            g_wsp4[b*NT + tid]  = wsp;
        }
        __syncthreads();
        if (tid < 6) {
            float s = 0.f;
            #pragma unroll
            for (int t = 0; t < NT; t++) s += s_slot[t][tid];
            g_bb[b*6 + tid] = s;                          // deterministic slot
        }
        // make this block's global writes (atomicOr, wcell, wsp4, bb) visible
        __threadfence();
        __syncthreads();

        // ---------- builder ticket: last builder does the union tail ----------
        if (tid == 0)
            s_flag = (atomicAdd(&g_bdone, 1) == NB - 1) ? 1 : 0;
        __syncthreads();
        if (s_flag) {
            __threadfence();   // acquire all builders' writes
            // snapshot union bitmap, reset for next replay
            unsigned w = 0u;
            float nzp = 0.f;
            if (tid < CELL_WORDS) {
                w = g_zero[tid];
                c_zero[tid] = w;
                g_zero[tid] = 0u;
                nzp = (float)__popc(w);
            }
            __syncthreads();
            // compact ignore-cell list
            if (tid < CELL_WORDS && w) {
                int n = __popc(w);
                int pos = atomicAdd(&s_nz, n);
                while (w) {
                    int bit = __ffs(w) - 1; w &= w - 1;
                    s_zlist[pos++] = tid * 32 + bit;
                }
            }
            __syncthreads();
            int nz = s_nz;

            // ignore-cell corrections: all 48 conf planes at each ignore cell
            float corr = 0.f;
            int pairs = 48 * nz;
            for (int i = tid; i < pairs; i += THREADS) {
                int cell = s_zlist[i / 48];
                int p = i % 48;
                float v = sample[(size_t)(85 * p + 4) * PLANE + (size_t)cell];
                corr += softplus_f(v);
            }
            // winner corrections: mask positions not inside an ignore cell
            float mcs = 0.f, mcc = 0.f;
            if (tid < NBT) {
                int cell = g_wcell[tid];
                if (cell >= 0 && !((c_zero[cell >> 5] >> (cell & 31)) & 1u)) {
                    mcs = g_wsp4[tid];
                    mcc = 1.f;
                }
            }
            corr = block_reduce1024(corr, s_red);
            mcs  = block_reduce1024(mcs,  s_red);
            mcc  = block_reduce1024(mcc,  s_red);
            nzp  = block_reduce1024(nzp,  s_red);
            if (tid == 0) {
                g_tail[0] = corr; g_tail[1] = mcs;
                g_tail[2] = mcc;  g_tail[3] = nzp;
                atomicExch(&g_bdone, 0);   // reset builder ticket
                __threadfence();
            }
        }
    }

    // ---------------- global ticket: lean final combine ----------------
    if (tid == 0)
        s_flag = (atomicAdd(&g_done, 1) == GRID - 1) ? 1 : 0;
    __syncthreads();
    if (s_flag) {
        __threadfence();   // acquire
        float dv = (tid < DENSE_BLOCKS) ? g_dense[tid] : 0.f;
        if (tid >= 32 && tid < 38) {       // warp 1: per-field batch sums
            int f = tid - 32;
            float s = 0.f;
            #pragma unroll
            for (int bb = 0; bb < NB; bb++) s += g_bb[bb*6 + f];
            s_f[f] = s;
        }
        if (tid >= 64 && tid < 68)         // warp 2: tail scalars
            s_t[tid - 64] = g_tail[tid - 64];
        float dsum = block_reduce1024(dv, s_red);   // ends with __syncthreads
        if (tid == 0) {
            float nm   = fmaxf(s_f[5], 1.f);
            float lx   = 2.0f * s_f[0] / nm;
            float ly   = 2.0f * s_f[1] / nm;
            float lw   = 1.6f * s_f[2] / nm;
            float lh   = 1.6f * s_f[3] / nm;
            float lobj = 1.0f * s_f[4] / nm;
            float ncnt = (float)TOTAL_CONF - 48.f * s_t[3] - s_t[2];
            float lnoobj = 0.5f * (dsum - s_t[0] - s_t[1]) / fmaxf(ncnt, 1.f);
            out[0] = lx + ly + lw + lh + lnoobj + lobj;
            out[1] = lx; out[2] = ly; out[3] = lw; out[4] = lh;
            out[5] = lobj; out[6] = lnoobj;
            atomicExch(&g_done, 0);   // graph-replay safe reset
        }
    }
}

extern "C" void kernel_launch(void* const* d_in, const int* in_sizes, int n_in,
                              void* d_out, int out_size)
{
    const float* sample  = (const float*)d_in[0];
    const float* targets = (const float*)d_in[1];
    const float* anchors = (const float*)d_in[2];
    float* out = (float*)d_out;

    k_yolo<<<GRID, THREADS>>>(sample, targets, anchors, out);
}